// round 10
// baseline (speedup 1.0000x reference)
#include <cuda_runtime.h>
#include <math.h>

#define NB 16
#define NT 2048
#define NF 768
#define NF4 (NF / 4)          // 192
#define EPSV 1e-5f
#define NCHUNK 16
#define TCHUNK (NT / NCHUNK)  // 128

// Persistent device state. All zero-initialized at module load.
// Invariant: k_final leaves g_acc* zeroed and g_ready == 0 after every launch,
// so every graph replay starts from a clean state (no host-side resets needed).
__device__ int   g_seq[NB];
__device__ int   g_ready;              // mask CTAs: +1 each; k_final resets to 0
__device__ float g_acc1[NB * NF];      // sum(x)   accumulators (REDG targets)
__device__ float g_acc2[NB * NF];      // sum(x^2) accumulators

// ---------------------------------------------------------------------------
// K1: fused mask + masked accumulation, no scratch round-trip.
// grid = (NCHUNK+1, NB) = 272 CTAs x 192 threads (all co-resident -> the
// flag spin below can never deadlock).
//   bx == NCHUNK : mask row-sum for batch b -> g_seq[b], release g_ready.
//   bx <  NCHUNK : stream full 128-row chunk unmasked (starts immediately),
//                  then spin (passes instantly: mask CTAs finished ~8us ago),
//                  subtract rows [max(t0,n), t0+128) (L1-hot re-read),
//                  REDG.F32 the 8 partials into the final accumulators.
// ---------------------------------------------------------------------------
__global__ void __launch_bounds__(192)
k_main(const float4* __restrict__ x4, const int4* __restrict__ mask4) {
    const int bx  = blockIdx.x;
    const int b   = blockIdx.y;
    const int tid = threadIdx.x;

    if (bx == NCHUNK) {
        // ---- mask sum for batch b ----
        int s = 0;
        const int4* mp = mask4 + b * (NT / 4);
        for (int i = tid; i < NT / 4; i += 192) {
            int4 v = mp[i];
            s += v.x + v.y + v.z + v.w;
        }
#pragma unroll
        for (int off = 16; off; off >>= 1)
            s += __shfl_down_sync(0xffffffffu, s, off);
        __shared__ int ws[6];
        if ((tid & 31) == 0) ws[tid >> 5] = s;
        __syncthreads();
        if (tid == 0) {
            int tot = 0;
#pragma unroll
            for (int w = 0; w < 6; w++) tot += ws[w];
            g_seq[b] = tot;
            __threadfence();               // release g_seq before the flag
            atomicAdd(&g_ready, 1);
        }
        return;
    }

    // ---- stream full 128-row chunk, unmasked (no gating on the mask) ----
    const int t0 = bx * TCHUNK;
    const float4* p = x4 + ((size_t)b * NT + (size_t)t0) * NF4 + tid;
    float4 s1 = make_float4(0.f, 0.f, 0.f, 0.f);
    float4 s2 = make_float4(0.f, 0.f, 0.f, 0.f);
#pragma unroll 8
    for (int t = 0; t < TCHUNK; t++, p += NF4) {
        float4 v = *p;
        s1.x += v.x; s1.y += v.y; s1.z += v.z; s1.w += v.w;
        s2.x = fmaf(v.x, v.x, s2.x);
        s2.y = fmaf(v.y, v.y, s2.y);
        s2.z = fmaf(v.z, v.z, s2.z);
        s2.w = fmaf(v.w, v.w, s2.w);
    }

    // ---- acquire n (mask CTAs are long finished; spin passes instantly) ----
    __shared__ int s_n;
    if (tid == 0) {
        while (*(volatile int*)&g_ready < NB) { }
        __threadfence();                   // acquire g_seq
        int sq[NB], smax = 0;
#pragma unroll
        for (int i = 0; i < NB; i++) {
            sq[i] = *(volatile int*)&g_seq[i];
            smax = max(smax, sq[i]);
        }
        // jnp fp32 semantics: divide, multiply by T, round-half-to-even
        const float rel = (float)sq[b] / (float)smax;
        s_n = (int)rintf(rel * (float)NT);
    }
    __syncthreads();
    const int n = s_n;

    // ---- subtract rows [max(t0,n), t0+128): most-recent rows -> L1-hot ----
    const int ts = max(t0, n);
    const int t1 = t0 + TCHUNK;
    const float4* q = x4 + ((size_t)b * NT + (size_t)ts) * NF4 + tid;
#pragma unroll 4
    for (int t = ts; t < t1; t++, q += NF4) {
        float4 v = *q;
        s1.x -= v.x; s1.y -= v.y; s1.z -= v.z; s1.w -= v.w;
        s2.x = fmaf(-v.x, v.x, s2.x);
        s2.y = fmaf(-v.y, v.y, s2.y);
        s2.z = fmaf(-v.z, v.z, s2.z);
        s2.w = fmaf(-v.w, v.w, s2.w);
    }

    // ---- reduce across chunks via fire-and-forget float atomics (L2) ----
    const int fb = b * NF + tid * 4;
    atomicAdd(&g_acc1[fb + 0], s1.x);
    atomicAdd(&g_acc1[fb + 1], s1.y);
    atomicAdd(&g_acc1[fb + 2], s1.z);
    atomicAdd(&g_acc1[fb + 3], s1.w);
    atomicAdd(&g_acc2[fb + 0], s2.x);
    atomicAdd(&g_acc2[fb + 1], s2.y);
    atomicAdd(&g_acc2[fb + 2], s2.z);
    atomicAdd(&g_acc2[fb + 3], s2.w);
}

// ---------------------------------------------------------------------------
// K2: trivial finalize. 48 CTAs x 256 threads, one thread per (b,f).
// Reads the just-written (L2-hot) accumulators, writes [B,1,2F], and restores
// the clean state (acc = 0, g_ready = 0) for the next graph replay.
// ---------------------------------------------------------------------------
__global__ void __launch_bounds__(256)
k_final(float* __restrict__ out) {
    const int i = blockIdx.x * 256 + threadIdx.x;   // 0 .. NB*NF-1
    const int b = i / NF;
    const int f = i - b * NF;

    const float s1 = g_acc1[i];
    const float s2 = g_acc2[i];

    int smax = 0;
#pragma unroll
    for (int k = 0; k < NB; k++) smax = max(smax, g_seq[k]);
    // jnp fp32 semantics: divide, multiply by T, round-half-to-even
    const float rel = (float)g_seq[b] / (float)smax;
    const float fn  = rintf(rel * (float)NT);

    const float mean = s1 / fn;
    const float var  = (s2 - mean * s1) / (fn - 1.0f);

    // NOTE: reference adds jax-threefry gauss noise in [1e-5, 9e-5] to mean.
    // Omitted: ~5e-5 normalized rel err (budget 1e-3, verified since R1).
    out[b * (2 * NF) + f]      = mean;
    out[b * (2 * NF) + NF + f] = sqrtf(var) + EPSV;

    // restore clean state for the next replay
    g_acc1[i] = 0.0f;
    g_acc2[i] = 0.0f;
    if (i == 0) g_ready = 0;
}

// ---------------------------------------------------------------------------
extern "C" void kernel_launch(void* const* d_in, const int* in_sizes, int n_in,
                              void* d_out, int out_size) {
    const float* x    = (const float*)d_in[0];   // [16,2048,768] f32
    const int*   mask = (const int*)d_in[1];     // [16,2048] i32
    float*       out  = (float*)d_out;           // [16,1,1536] f32

    k_main<<<dim3(NCHUNK + 1, NB), 192>>>((const float4*)x, (const int4*)mask);
    k_final<<<NB * NF / 256, 256>>>(out);
}

// round 11
// speedup vs baseline: 1.5550x; 1.5550x over previous
#include <cuda_runtime.h>
#include <math.h>

#define NB 16
#define NT 2048
#define NF 768
#define NF4 (NF / 4)          // 192
#define EPSV 1e-5f
#define TSPLIT 64
#define TCHUNK (NT / TSPLIT)  // 32

// Persistent device state, zero-initialized at load.
// Invariant: k_final resets g_ready to 0 each launch -> replay-safe.
// All other slots are unconditionally overwritten every launch.
__device__ int    g_seq[NB];
__device__ int    g_ready;                    // mask CTAs +1; k_final resets
__device__ int    g_actual[NB];               // n per batch (boundary CTAs)
__device__ float4 g_S1[NB * NF4 * TSPLIT];    // transposed chunk partials
__device__ float4 g_S2[NB * NF4 * TSPLIT];
__device__ float4 g_B1[NB * NF4];             // boundary-row partials
__device__ float4 g_B2[NB * NF4];

// ---------------------------------------------------------------------------
// K1: grid (TSPLIT+2, NB) = 1056 CTAs x 192 threads.
//   bx == 0 : mask row-sum for batch b -> g_seq[b]; release g_ready.
//   bx == 1 : boundary CTA for batch b: spin for g_ready==16 (mask CTAs never
//             wait on anything -> no circular wait), compute n -> g_actual[b],
//             accumulate rows [32*(n/32), n) -> g_B1/g_B2. Hidden under the
//             ~10us of streaming done by the 1024 chunk CTAs.
//   bx >= 2 : unmasked 32-row chunk partials (R9 structure, untouched).
// ---------------------------------------------------------------------------
__global__ void __launch_bounds__(192)
k_main(const float4* __restrict__ x4, const int4* __restrict__ mask4) {
    const int bx  = blockIdx.x;
    const int b   = blockIdx.y;
    const int tid = threadIdx.x;

    if (bx == 0) {
        // ---- mask sum for batch b ----
        int s = 0;
        const int4* mp = mask4 + b * (NT / 4);
        for (int i = tid; i < NT / 4; i += 192) {
            int4 v = mp[i];
            s += v.x + v.y + v.z + v.w;
        }
#pragma unroll
        for (int off = 16; off; off >>= 1)
            s += __shfl_down_sync(0xffffffffu, s, off);
        __shared__ int ws[6];
        if ((tid & 31) == 0) ws[tid >> 5] = s;
        __syncthreads();
        if (tid == 0) {
            int tot = 0;
#pragma unroll
            for (int w = 0; w < 6; w++) tot += ws[w];
            g_seq[b] = tot;
            __threadfence();               // release g_seq before flag
            atomicAdd(&g_ready, 1);
        }
        return;
    }

    if (bx == 1) {
        // ---- boundary CTA for batch b ----
        __shared__ int s_n;
        if (tid == 0) {
            while (*(volatile int*)&g_ready < NB) { }
            __threadfence();               // acquire g_seq
            int smax = 0, sb = 0;
#pragma unroll
            for (int i = 0; i < NB; i++) {
                int v = *(volatile int*)&g_seq[i];
                smax = max(smax, v);
                if (i == b) sb = v;
            }
            // jnp fp32 semantics: divide, mul by T, round-half-to-even
            const float rel = (float)sb / (float)smax;
            const int   n   = (int)rintf(rel * (float)NT);
            g_actual[b] = n;
            s_n = n;
        }
        __syncthreads();
        const int n  = s_n;
        const int tb = (n / TCHUNK) * TCHUNK;

        float4 s1 = make_float4(0.f, 0.f, 0.f, 0.f);
        float4 s2 = make_float4(0.f, 0.f, 0.f, 0.f);
        const float4* q = x4 + ((size_t)b * NT + (size_t)tb) * NF4 + tid;
#pragma unroll 8
        for (int t = tb; t < n; t++, q += NF4) {
            float4 v = *q;
            s1.x += v.x; s1.y += v.y; s1.z += v.z; s1.w += v.w;
            s2.x = fmaf(v.x, v.x, s2.x);
            s2.y = fmaf(v.y, v.y, s2.y);
            s2.z = fmaf(v.z, v.z, s2.z);
            s2.w = fmaf(v.w, v.w, s2.w);
        }
        g_B1[b * NF4 + tid] = s1;          // written even if empty (zeros)
        g_B2[b * NF4 + tid] = s2;
        return;
    }

    // ---- unmasked partial over a full 32-row chunk (ts = bx - 2) ----
    const int ts = bx - 2;
    const float4* p = x4 + ((size_t)b * NT + (size_t)ts * TCHUNK) * NF4 + tid;
    float4 s1 = make_float4(0.f, 0.f, 0.f, 0.f);
    float4 s2 = make_float4(0.f, 0.f, 0.f, 0.f);
#pragma unroll 8
    for (int t = 0; t < TCHUNK; t++, p += NF4) {
        float4 v = *p;
        s1.x += v.x; s1.y += v.y; s1.z += v.z; s1.w += v.w;
        s2.x = fmaf(v.x, v.x, s2.x);
        s2.y = fmaf(v.y, v.y, s2.y);
        s2.z = fmaf(v.z, v.z, s2.z);
        s2.w = fmaf(v.w, v.w, s2.w);
    }
    // transposed slot store: k_final warp reads slots with lane index
    const int idx = (b * NF4 + tid) * TSPLIT + ts;
    g_S1[idx] = s1;
    g_S2[idx] = s2;
}

// ---------------------------------------------------------------------------
// K2: single-round finalize. One warp per (b, f4); 7 independent loads
// (4 slot float4s via lanes, boundary pair, g_actual), predicated add,
// warp-shfl tree, lane 0 folds boundary + finalizes. No second memory round.
// grid = NB*NF4/8 = 384 CTAs, block = 256 (8 warps). Also resets g_ready.
// ---------------------------------------------------------------------------
__global__ void __launch_bounds__(256)
k_final(float4* __restrict__ out4) {
    const int gw   = blockIdx.x * 8 + (threadIdx.x >> 5);  // b*NF4 + f4
    const int lane = threadIdx.x & 31;
    const int b    = gw / NF4;
    const int f4   = gw - b * NF4;

    // ---- all loads independent: issue together, one memory round ----
    const float4* S1 = g_S1 + (size_t)gw * TSPLIT;
    const float4* S2 = g_S2 + (size_t)gw * TSPLIT;
    float4 a0 = S1[lane];
    float4 a1 = S1[lane + 32];
    float4 c0 = S2[lane];
    float4 c1 = S2[lane + 32];
    float4 b1 = g_B1[gw];                 // warp-broadcast
    float4 b2 = g_B2[gw];
    const int n  = g_actual[b];           // warp-broadcast
    const int cb = n / TCHUNK;

    float4 s1 = make_float4(0.f, 0.f, 0.f, 0.f);
    float4 s2 = make_float4(0.f, 0.f, 0.f, 0.f);
    if (lane < cb) {
        s1.x += a0.x; s1.y += a0.y; s1.z += a0.z; s1.w += a0.w;
        s2.x += c0.x; s2.y += c0.y; s2.z += c0.z; s2.w += c0.w;
    }
    if (lane + 32 < cb) {
        s1.x += a1.x; s1.y += a1.y; s1.z += a1.z; s1.w += a1.w;
        s2.x += c1.x; s2.y += c1.y; s2.z += c1.z; s2.w += c1.w;
    }

    // ---- warp tree reduction (8 floats) ----
#pragma unroll
    for (int off = 16; off; off >>= 1) {
        s1.x += __shfl_down_sync(0xffffffffu, s1.x, off);
        s1.y += __shfl_down_sync(0xffffffffu, s1.y, off);
        s1.z += __shfl_down_sync(0xffffffffu, s1.z, off);
        s1.w += __shfl_down_sync(0xffffffffu, s1.w, off);
        s2.x += __shfl_down_sync(0xffffffffu, s2.x, off);
        s2.y += __shfl_down_sync(0xffffffffu, s2.y, off);
        s2.z += __shfl_down_sync(0xffffffffu, s2.z, off);
        s2.w += __shfl_down_sync(0xffffffffu, s2.w, off);
    }

    if (lane == 0) {
        // fold in boundary-row partials
        s1.x += b1.x; s1.y += b1.y; s1.z += b1.z; s1.w += b1.w;
        s2.x += b2.x; s2.y += b2.y; s2.z += b2.z; s2.w += b2.w;

        const float fn  = (float)n;
        const float inv = 1.0f / fn;
        const float idd = 1.0f / (fn - 1.0f);

        float4 mean, sd;
        mean.x = s1.x * inv; mean.y = s1.y * inv;
        mean.z = s1.z * inv; mean.w = s1.w * inv;
        sd.x = sqrtf((s2.x - mean.x * s1.x) * idd) + EPSV;
        sd.y = sqrtf((s2.y - mean.y * s1.y) * idd) + EPSV;
        sd.z = sqrtf((s2.z - mean.z * s1.z) * idd) + EPSV;
        sd.w = sqrtf((s2.w - mean.w * s1.w) * idd) + EPSV;

        // NOTE: reference adds jax-threefry gauss noise in [1e-5, 9e-5] to
        // mean. Omitted: ~5e-5 normalized rel err (budget 1e-3, verified R1).
        out4[b * (2 * NF4) + f4]       = mean;   // [B,1,2F]: mean | std
        out4[b * (2 * NF4) + NF4 + f4] = sd;
    }

    if (gw == 0 && lane == 0) g_ready = 0;   // clean state for next replay
}

// ---------------------------------------------------------------------------
extern "C" void kernel_launch(void* const* d_in, const int* in_sizes, int n_in,
                              void* d_out, int out_size) {
    const float* x    = (const float*)d_in[0];   // [16,2048,768] f32
    const int*   mask = (const int*)d_in[1];     // [16,2048] i32
    float*       out  = (float*)d_out;           // [16,1,1536] f32

    k_main<<<dim3(TSPLIT + 2, NB), 192>>>((const float4*)x, (const int4*)mask);
    k_final<<<NB * NF4 / 8, 256>>>((float4*)out);
}